// round 10
// baseline (speedup 1.0000x reference)
#include <cuda_runtime.h>
#include <cuda_fp16.h>
#include <cstdint>

// QKVAttentionLegacy: qkv (4,1536,2048) fp32 -> out (4,512,2048) fp32.
// 32 heads, ch=64, seq=2048.
//  1) cvt_kv: K/V fp32 -> fp16 scratch (Q handled in-kernel).
//  2) attention: cp.async double-buffered K/V fp16 (BN=128), ldmatrix(.trans),
//     mma.sync.m16n8k16 fp16, exp2-domain softmax (no online max).
//     Critical-path cuts: split G1 accumulator chains (depth 4->2),
//     register-prefetched K fragments for kt+1, 4-way lsum accumulators.

#define SEQ     2048
#define QSCALE  0.18033688011112042f   // 0.125 * log2(e)

// smem tiles: [64 c][136 halves] (stride 68 words = 4 mod 32 -> conflict-free)
#define TILE_B  17408
#define OFF_Q   0
#define OFF_K0  17408
#define OFF_V0  34816
#define OFF_K1  52224
#define OFF_V1  69632
#define SMEM_BYTES 87040
#define OFF_OUT OFF_K0       // epilogue overlay: 64*132*4 = 33792 B
#define OSTR 132

__device__ __half qkv_h[4 * 1536 * 2048];   // fp16 scratch (K/V regions used)

__device__ __forceinline__ float ex2f(float x) {
    float y; asm("ex2.approx.f32 %0, %1;" : "=f"(y) : "f"(x)); return y;
}
__device__ __forceinline__ uint32_t packh2(float a, float b) {
    __half2 h = __floats2half2_rn(a, b);
    return *(uint32_t*)&h;
}
__device__ __forceinline__ void mma_f16(float* d, const uint32_t* a,
                                        uint32_t b0, uint32_t b1) {
    asm volatile("mma.sync.aligned.m16n8k16.row.col.f32.f16.f16.f32 "
        "{%0,%1,%2,%3}, {%4,%5,%6,%7}, {%8,%9}, {%0,%1,%2,%3};"
        : "+f"(d[0]), "+f"(d[1]), "+f"(d[2]), "+f"(d[3])
        : "r"(a[0]), "r"(a[1]), "r"(a[2]), "r"(a[3]), "r"(b0), "r"(b1));
}
__device__ __forceinline__ void ldsm4(uint32_t& r0, uint32_t& r1,
                                      uint32_t& r2, uint32_t& r3, uint32_t a) {
    asm volatile("ldmatrix.sync.aligned.m8n8.x4.shared.b16 {%0,%1,%2,%3}, [%4];"
        : "=r"(r0), "=r"(r1), "=r"(r2), "=r"(r3) : "r"(a));
}
__device__ __forceinline__ void ldsm4t(uint32_t& r0, uint32_t& r1,
                                       uint32_t& r2, uint32_t& r3, uint32_t a) {
    asm volatile("ldmatrix.sync.aligned.m8n8.x4.trans.shared.b16 {%0,%1,%2,%3}, [%4];"
        : "=r"(r0), "=r"(r1), "=r"(r2), "=r"(r3) : "r"(a));
}
__device__ __forceinline__ void cpa16(uint32_t dst, const void* src) {
    asm volatile("cp.async.cg.shared.global [%0], [%1], 16;"
                 :: "r"(dst), "l"(src) : "memory");
}
#define CP_COMMIT() asm volatile("cp.async.commit_group;" ::: "memory")
#define CP_WAIT(n)  asm volatile("cp.async.wait_group %0;" :: "n"(n) : "memory")

// ---- pre-pass: K/V rows fp32 -> fp16 (Q rows untouched) ----
__global__ void __launch_bounds__(256)
cvt_kv(const float* __restrict__ qkv) {
    const int flat = (blockIdx.x * 256 + threadIdx.x) * 8;
    const int r    = flat >> 11;                 // 0..4095 (K/V row id)
    const int col  = flat & 2047;
    const int row  = (r >> 7) * 192 + 64 + (r & 127);
    const float* src = qkv + (size_t)row * 2048 + col;
    float4 a = *(const float4*)src;
    float4 b = *(const float4*)(src + 4);
    uint4 u;
    u.x = packh2(a.x, a.y); u.y = packh2(a.z, a.w);
    u.z = packh2(b.x, b.y); u.w = packh2(b.z, b.w);
    *(uint4*)(qkv_h + (size_t)row * 2048 + col) = u;
}

// ---- attention kernel ----
__global__ void __launch_bounds__(256, 2)
qkv_attn_async(const float* __restrict__ qkv, float* __restrict__ out) {
    extern __shared__ char smem[];
    const uint32_t sbase = (uint32_t)__cvta_generic_to_shared(smem);
    const int tid  = threadIdx.x;
    const int H    = blockIdx.y;
    const int t0   = blockIdx.x * 128;
    const int w    = tid >> 5;
    const int lane = tid & 31;
    const int g    = lane >> 2;
    const int tg   = lane & 3;
    const int lrow = lane & 7;
    const int lm   = lane >> 3;          // matrix index within ldmatrix.x4

    const float*  qgf = qkv + (size_t)(H * 192) * SEQ;          // fp32 Q
    const __half* kg  = qkv_h + (size_t)(H * 192 + 64) * SEQ;   // fp16 K
    const __half* vg  = qkv_h + (size_t)(H * 192 + 128) * SEQ;  // fp16 V
    float* outg = out + (size_t)(H * 64) * SEQ;

    const uint32_t kbuf[2] = { sbase + OFF_K0, sbase + OFF_K1 };
    const uint32_t vbuf[2] = { sbase + OFF_V0, sbase + OFF_V1 };

    // per-lane constant ldmatrix offsets (bytes)
    uint32_t koff[2];
#pragma unroll
    for (int kqp = 0; kqp < 2; kqp++)
        koff[kqp] = (uint32_t)(((kqp * 32 + (lm >> 1) * 16 + (lm & 1) * 8 + lrow)
                                * 136) * 2);
    uint32_t voff[4];
#pragma unroll
    for (int jcp = 0; jcp < 4; jcp++)
        voff[jcp] = (uint32_t)(((jcp * 2 + (lm >> 1)) * 8 + lrow) * 136 * 2
                               + (lm & 1) * 16);

    // ---- issue tile-0 K/V cp.async first (fly while Q stages) ----
#pragma unroll
    for (int it = 0; it < 4; it++) {
        int task = tid + it * 256;
        int c  = task >> 4;
        int ch = (task & 15) << 3;
        cpa16(kbuf[0] + (uint32_t)((c * 136 + ch) * 2), kg + (size_t)c * SEQ + ch);
        cpa16(vbuf[0] + (uint32_t)((c * 136 + ch) * 2), vg + (size_t)c * SEQ + ch);
    }
    CP_COMMIT();

    // ---- stage Q: fp32 LDG -> prescaled fp16 [c][t] ----
#pragma unroll
    for (int it = 0; it < 4; it++) {
        int task = tid + it * 256;           // (c, t8): 64 x 16
        int c  = task >> 4;
        int t8 = (task & 15) << 3;
        const float* src = qgf + (size_t)c * SEQ + t0 + t8;
        float4 a = *(const float4*)src;
        float4 b = *(const float4*)(src + 4);
        uint4 u;
        u.x = packh2(a.x * QSCALE, a.y * QSCALE);
        u.y = packh2(a.z * QSCALE, a.w * QSCALE);
        u.z = packh2(b.x * QSCALE, b.y * QSCALE);
        u.w = packh2(b.z * QSCALE, b.w * QSCALE);
        *(uint4*)(smem + OFF_Q + (uint32_t)((c * 136 + t8) * 2)) = u;
    }

    uint32_t aq[4][4];
    float o[8][4];
#pragma unroll
    for (int jc = 0; jc < 8; jc++)
#pragma unroll
        for (int r = 0; r < 4; r++) o[jc][r] = 0.0f;
    float lsA0 = 0.f, lsA1 = 0.f, lsB0 = 0.f, lsB1 = 0.f;

    for (int i = 0; i < 16; i++) {
        if (i < 15) {
            const int sb = (i + 1) * 128;
            const uint32_t kn = kbuf[(i + 1) & 1], vn = vbuf[(i + 1) & 1];
#pragma unroll
            for (int it = 0; it < 4; it++) {
                int task = tid + it * 256;
                int c  = task >> 4;
                int ch = (task & 15) << 3;
                cpa16(kn + (uint32_t)((c * 136 + ch) * 2),
                      kg + (size_t)c * SEQ + sb + ch);
                cpa16(vn + (uint32_t)((c * 136 + ch) * 2),
                      vg + (size_t)c * SEQ + sb + ch);
            }
            CP_COMMIT();
            CP_WAIT(1);
        } else {
            CP_WAIT(0);
        }
        __syncthreads();

        if (i == 0) {   // Q A-fragments via trans ldmatrix from [c][t]
#pragma unroll
            for (int kq = 0; kq < 4; kq++) {
                uint32_t qa = sbase + OFF_Q
                    + (uint32_t)(((kq * 16 + (lm >> 1) * 8 + lrow) * 136
                                  + w * 16 + (lm & 1) * 8) * 2);
                ldsm4t(aq[kq][0], aq[kq][1], aq[kq][2], aq[kq][3], qa);
            }
        }

        const uint32_t kb = kbuf[i & 1], vb = vbuf[i & 1];

        // K fragments for kt=0 (indices: [jj*8 + kqp*4 + m])
        uint32_t kfc[16];
        ldsm4t(kfc[0],  kfc[1],  kfc[2],  kfc[3],  kb + koff[0]);
        ldsm4t(kfc[4],  kfc[5],  kfc[6],  kfc[7],  kb + koff[1]);
        ldsm4t(kfc[8],  kfc[9],  kfc[10], kfc[11], kb + koff[0] + 16);
        ldsm4t(kfc[12], kfc[13], kfc[14], kfc[15], kb + koff[1] + 16);

#pragma unroll
        for (int kt = 0; kt < 8; kt++) {
            // ---- GEMM1: two 2-deep chains per jj ----
            float accA[2][4], accB[2][4];
#pragma unroll
            for (int jj = 0; jj < 2; jj++) {
                const uint32_t* f = kfc + jj * 8;
#pragma unroll
                for (int r = 0; r < 4; r++) { accA[jj][r] = 0.f; accB[jj][r] = 0.f; }
                mma_f16(accA[jj], aq[0], f[0], f[1]);
                mma_f16(accA[jj], aq[1], f[2], f[3]);
                mma_f16(accB[jj], aq[2], f[4], f[5]);
                mma_f16(accB[jj], aq[3], f[6], f[7]);
            }

            // ---- prefetch next kt's K fragments ----
            uint32_t kfn[16];
            if (kt < 7) {
                const uint32_t so = (uint32_t)((kt + 1) * 32);
                ldsm4t(kfn[0],  kfn[1],  kfn[2],  kfn[3],  kb + koff[0] + so);
                ldsm4t(kfn[4],  kfn[5],  kfn[6],  kfn[7],  kb + koff[1] + so);
                ldsm4t(kfn[8],  kfn[9],  kfn[10], kfn[11], kb + koff[0] + so + 16);
                ldsm4t(kfn[12], kfn[13], kfn[14], kfn[15], kb + koff[1] + so + 16);
            }

            // ---- merge + softmax (exp2 domain) ----
            uint32_t ph[4];
            {
                float e0 = ex2f(accA[0][0] + accB[0][0]);
                float e1 = ex2f(accA[0][1] + accB[0][1]);
                float e2 = ex2f(accA[0][2] + accB[0][2]);
                float e3 = ex2f(accA[0][3] + accB[0][3]);
                lsA0 += e0 + e1;
                lsA1 += e2 + e3;
                ph[0] = packh2(e0, e1);
                ph[1] = packh2(e2, e3);
            }
            {
                float e0 = ex2f(accA[1][0] + accB[1][0]);
                float e1 = ex2f(accA[1][1] + accB[1][1]);
                float e2 = ex2f(accA[1][2] + accB[1][2]);
                float e3 = ex2f(accA[1][3] + accB[1][3]);
                lsB0 += e0 + e1;
                lsB1 += e2 + e3;
                ph[2] = packh2(e0, e1);
                ph[3] = packh2(e2, e3);
            }

            // ---- GEMM2: O += P * V^T ----
#pragma unroll
            for (int jcp = 0; jcp < 4; jcp++) {
                uint32_t b0, b1, b2, b3;
                ldsm4(b0, b1, b2, b3, vb + voff[jcp] + (uint32_t)(kt * 32));
                mma_f16(o[jcp * 2 + 0], ph, b0, b1);
                mma_f16(o[jcp * 2 + 1], ph, b2, b3);
            }

#pragma unroll
            for (int t = 0; t < 16; t++) kfc[t] = kfn[t];
        }
        __syncthreads();   // done reading buf[i&1] before issue(i+1) reuses it
    }

    // ---- epilogue: row sums, normalize, transpose via smem, store ----
    float lsum0 = lsA0 + lsB0;
    float lsum1 = lsA1 + lsB1;
    lsum0 += __shfl_xor_sync(0xffffffffu, lsum0, 1);
    lsum0 += __shfl_xor_sync(0xffffffffu, lsum0, 2);
    lsum1 += __shfl_xor_sync(0xffffffffu, lsum1, 1);
    lsum1 += __shfl_xor_sync(0xffffffffu, lsum1, 2);
    const float inv0 = 1.0f / lsum0;
    const float inv1 = 1.0f / lsum1;
    const int row0 = w * 16 + g;

    float* outs = (float*)(smem + OFF_OUT);   // [c][t], stride OSTR
#pragma unroll
    for (int jc = 0; jc < 8; jc++) {
        int c = jc * 8 + tg * 2;
        outs[(c + 0) * OSTR + row0]     = o[jc][0] * inv0;
        outs[(c + 1) * OSTR + row0]     = o[jc][1] * inv0;
        outs[(c + 0) * OSTR + row0 + 8] = o[jc][2] * inv1;
        outs[(c + 1) * OSTR + row0 + 8] = o[jc][3] * inv1;
    }
    __syncthreads();
#pragma unroll
    for (int it = 0; it < 8; it++) {
        int task = tid + it * 256;           // (c, t4): 64 x 32
        int c  = task >> 5;
        int t4 = (task & 31) << 2;
        *(float4*)(outg + (size_t)c * SEQ + t0 + t4) =
            *(const float4*)(outs + c * OSTR + t4);
    }
}

extern "C" void kernel_launch(void* const* d_in, const int* in_sizes, int n_in,
                              void* d_out, int out_size) {
    const float* qkv = (const float*)d_in[0];
    float* out = (float*)d_out;
    cvt_kv<<<4096, 256>>>(qkv);
    cudaFuncSetAttribute(qkv_attn_async,
                         cudaFuncAttributeMaxDynamicSharedMemorySize, SMEM_BYTES);
    dim3 grid(SEQ / 128, 32);
    qkv_attn_async<<<grid, 256, SMEM_BYTES>>>(qkv, out);
}

// round 13
// speedup vs baseline: 1.1306x; 1.1306x over previous
#include <cuda_runtime.h>
#include <cuda_fp16.h>
#include <cstdint>

// QKVAttentionLegacy: qkv (4,1536,2048) fp32 -> out (4,512,2048) fp32.
// 32 heads, ch=64, seq=2048.
//  1) cvt_kv: K/V fp32 -> fp16 scratch (Q staged in-kernel from fp32).
//  2) attention: cp.async double-buffered K/V fp16 (BN=128), ldmatrix(.trans),
//     mma.sync.m16n8k16 fp16, exp2-domain softmax (no online max).
//     Softmax denominator via one HMMA against an all-ones B fragment
//     (lacc += P x 1): zero FADDs, zero epilogue shuffles, l consistent with
//     the numerator's fp16 P.
// R11 bugfix: GEMM1 K ldsm offset now includes the jj half (so + jj*16 B);
// round 11 read the same 8 s-columns for both halves -> rel_err 0.8.

#define SEQ     2048
#define QSCALE  0.18033688011112042f   // 0.125 * log2(e)

// smem tiles: [64 c][136 halves] (stride 68 words = 4 mod 32 -> conflict-free)
#define OFF_Q   0
#define OFF_K0  17408
#define OFF_V0  34816
#define OFF_K1  52224
#define OFF_V1  69632
#define SMEM_BYTES 87040
#define OFF_OUT OFF_K0       // epilogue overlay: 64*132*4 = 33792 B
#define OSTR 132

__device__ __half qkv_h[4 * 1536 * 2048];   // fp16 scratch (K/V regions used)

__device__ __forceinline__ float ex2f(float x) {
    float y; asm("ex2.approx.f32 %0, %1;" : "=f"(y) : "f"(x)); return y;
}
__device__ __forceinline__ uint32_t packh2(float a, float b) {
    __half2 h = __floats2half2_rn(a, b);
    return *(uint32_t*)&h;
}
__device__ __forceinline__ void mma_f16(float* d, const uint32_t* a,
                                        uint32_t b0, uint32_t b1) {
    asm volatile("mma.sync.aligned.m16n8k16.row.col.f32.f16.f16.f32 "
        "{%0,%1,%2,%3}, {%4,%5,%6,%7}, {%8,%9}, {%0,%1,%2,%3};"
        : "+f"(d[0]), "+f"(d[1]), "+f"(d[2]), "+f"(d[3])
        : "r"(a[0]), "r"(a[1]), "r"(a[2]), "r"(a[3]), "r"(b0), "r"(b1));
}
__device__ __forceinline__ void ldsm4(uint32_t& r0, uint32_t& r1,
                                      uint32_t& r2, uint32_t& r3, uint32_t a) {
    asm volatile("ldmatrix.sync.aligned.m8n8.x4.shared.b16 {%0,%1,%2,%3}, [%4];"
        : "=r"(r0), "=r"(r1), "=r"(r2), "=r"(r3) : "r"(a));
}
__device__ __forceinline__ void ldsm4t(uint32_t& r0, uint32_t& r1,
                                       uint32_t& r2, uint32_t& r3, uint32_t a) {
    asm volatile("ldmatrix.sync.aligned.m8n8.x4.trans.shared.b16 {%0,%1,%2,%3}, [%4];"
        : "=r"(r0), "=r"(r1), "=r"(r2), "=r"(r3) : "r"(a));
}
__device__ __forceinline__ void cpa16(uint32_t dst, const void* src) {
    asm volatile("cp.async.cg.shared.global [%0], [%1], 16;"
                 :: "r"(dst), "l"(src) : "memory");
}
#define CP_COMMIT() asm volatile("cp.async.commit_group;" ::: "memory")
#define CP_WAIT(n)  asm volatile("cp.async.wait_group %0;" :: "n"(n) : "memory")

// ---- pre-pass: K/V rows fp32 -> fp16 (Q rows untouched) ----
__global__ void __launch_bounds__(256)
cvt_kv(const float* __restrict__ qkv) {
    const int flat = (blockIdx.x * 256 + threadIdx.x) * 8;
    const int r    = flat >> 11;                 // 0..4095 (K/V row id)
    const int col  = flat & 2047;
    const int row  = (r >> 7) * 192 + 64 + (r & 127);
    const float* src = qkv + (size_t)row * 2048 + col;
    float4 a = *(const float4*)src;
    float4 b = *(const float4*)(src + 4);
    uint4 u;
    u.x = packh2(a.x, a.y); u.y = packh2(a.z, a.w);
    u.z = packh2(b.x, b.y); u.w = packh2(b.z, b.w);
    *(uint4*)(qkv_h + (size_t)row * 2048 + col) = u;
}

// ---- attention kernel ----
__global__ void __launch_bounds__(256, 2)
qkv_attn_async(const float* __restrict__ qkv, float* __restrict__ out) {
    extern __shared__ char smem[];
    const uint32_t sbase = (uint32_t)__cvta_generic_to_shared(smem);
    const int tid  = threadIdx.x;
    const int H    = blockIdx.y;
    const int t0   = blockIdx.x * 128;
    const int w    = tid >> 5;
    const int lane = tid & 31;
    const int g    = lane >> 2;
    const int tg   = lane & 3;
    const int lrow = lane & 7;
    const int lm   = lane >> 3;          // matrix index within ldmatrix.x4

    const float*  qgf = qkv + (size_t)(H * 192) * SEQ;          // fp32 Q
    const __half* kg  = qkv_h + (size_t)(H * 192 + 64) * SEQ;   // fp16 K
    const __half* vg  = qkv_h + (size_t)(H * 192 + 128) * SEQ;  // fp16 V
    float* outg = out + (size_t)(H * 64) * SEQ;

    const uint32_t kbuf[2] = { sbase + OFF_K0, sbase + OFF_K1 };
    const uint32_t vbuf[2] = { sbase + OFF_V0, sbase + OFF_V1 };
    const uint32_t ONES = 0x3C003C00u;   // fp16x2 {1,1}

    // per-lane constant ldmatrix offsets (bytes)
    uint32_t koff[2];
#pragma unroll
    for (int kqp = 0; kqp < 2; kqp++)
        koff[kqp] = (uint32_t)(((kqp * 32 + (lm >> 1) * 16 + (lm & 1) * 8 + lrow)
                                * 136) * 2);
    uint32_t voff[4];
#pragma unroll
    for (int jcp = 0; jcp < 4; jcp++)
        voff[jcp] = (uint32_t)(((jcp * 2 + (lm >> 1)) * 8 + lrow) * 136 * 2
                               + (lm & 1) * 16);

    // ---- issue tile-0 K/V cp.async first (fly while Q stages) ----
#pragma unroll
    for (int it = 0; it < 4; it++) {
        int task = tid + it * 256;
        int c  = task >> 4;
        int ch = (task & 15) << 3;
        cpa16(kbuf[0] + (uint32_t)((c * 136 + ch) * 2), kg + (size_t)c * SEQ + ch);
        cpa16(vbuf[0] + (uint32_t)((c * 136 + ch) * 2), vg + (size_t)c * SEQ + ch);
    }
    CP_COMMIT();

    // ---- stage Q: fp32 LDG -> prescaled fp16 [c][t] ----
#pragma unroll
    for (int it = 0; it < 4; it++) {
        int task = tid + it * 256;           // (c, t8): 64 x 16
        int c  = task >> 4;
        int t8 = (task & 15) << 3;
        const float* src = qgf + (size_t)c * SEQ + t0 + t8;
        float4 a = *(const float4*)src;
        float4 b = *(const float4*)(src + 4);
        uint4 u;
        u.x = packh2(a.x * QSCALE, a.y * QSCALE);
        u.y = packh2(a.z * QSCALE, a.w * QSCALE);
        u.z = packh2(b.x * QSCALE, b.y * QSCALE);
        u.w = packh2(b.z * QSCALE, b.w * QSCALE);
        *(uint4*)(smem + OFF_Q + (uint32_t)((c * 136 + t8) * 2)) = u;
    }

    uint32_t aq[4][4];
    float o[8][4];
#pragma unroll
    for (int jc = 0; jc < 8; jc++)
#pragma unroll
        for (int r = 0; r < 4; r++) o[jc][r] = 0.0f;
    float lacc[4] = {0.f, 0.f, 0.f, 0.f};   // ones-column row sums

    for (int i = 0; i < 16; i++) {
        if (i < 15) {
            const int sb = (i + 1) * 128;
            const uint32_t kn = kbuf[(i + 1) & 1], vn = vbuf[(i + 1) & 1];
#pragma unroll
            for (int it = 0; it < 4; it++) {
                int task = tid + it * 256;
                int c  = task >> 4;
                int ch = (task & 15) << 3;
                cpa16(kn + (uint32_t)((c * 136 + ch) * 2),
                      kg + (size_t)c * SEQ + sb + ch);
                cpa16(vn + (uint32_t)((c * 136 + ch) * 2),
                      vg + (size_t)c * SEQ + sb + ch);
            }
            CP_COMMIT();
            CP_WAIT(1);
        } else {
            CP_WAIT(0);
        }
        __syncthreads();

        if (i == 0) {   // Q A-fragments via trans ldmatrix from [c][t]
#pragma unroll
            for (int kq = 0; kq < 4; kq++) {
                uint32_t qa = sbase + OFF_Q
                    + (uint32_t)(((kq * 16 + (lm >> 1) * 8 + lrow) * 136
                                  + w * 16 + (lm & 1) * 8) * 2);
                ldsm4t(aq[kq][0], aq[kq][1], aq[kq][2], aq[kq][3], qa);
            }
        }

        const uint32_t kb = kbuf[i & 1], vb = vbuf[i & 1];
#pragma unroll
        for (int kt = 0; kt < 8; kt++) {
            const uint32_t so = (uint32_t)(kt * 32);
            float acc[2][4];
#pragma unroll
            for (int jj = 0; jj < 2; jj++) {
                const uint32_t sj = so + (uint32_t)(jj * 16);  // jj's 8 s-cols
                acc[jj][0] = 0.f; acc[jj][1] = 0.f;
                acc[jj][2] = 0.f; acc[jj][3] = 0.f;
                uint32_t b0, b1, b2, b3;
                ldsm4t(b0, b1, b2, b3, kb + koff[0] + sj);
                mma_f16(acc[jj], aq[0], b0, b1);
                mma_f16(acc[jj], aq[1], b2, b3);
                ldsm4t(b0, b1, b2, b3, kb + koff[1] + sj);
                mma_f16(acc[jj], aq[2], b0, b1);
                mma_f16(acc[jj], aq[3], b2, b3);
            }

            // softmax (exp2 domain) -> fp16 P fragment
            uint32_t ph[4];
#pragma unroll
            for (int jj = 0; jj < 2; jj++) {
                float e0 = ex2f(acc[jj][0]);
                float e1 = ex2f(acc[jj][1]);
                float e2 = ex2f(acc[jj][2]);
                float e3 = ex2f(acc[jj][3]);
                ph[jj * 2 + 0] = packh2(e0, e1);
                ph[jj * 2 + 1] = packh2(e2, e3);
            }

            // denominator: lacc += P x Ones (full row sum, no shuffles)
            mma_f16(lacc, ph, ONES, ONES);

            // GEMM2: O += P * V^T
#pragma unroll
            for (int jcp = 0; jcp < 4; jcp++) {
                uint32_t b0, b1, b2, b3;
                ldsm4(b0, b1, b2, b3, vb + voff[jcp] + so);
                mma_f16(o[jcp * 2 + 0], ph, b0, b1);
                mma_f16(o[jcp * 2 + 1], ph, b2, b3);
            }
        }
        __syncthreads();   // done reading buf[i&1] before next issue reuses it
    }

    // ---- epilogue: normalize (lacc holds full row sums), store ----
    const float inv0 = 1.0f / lacc[0];
    const float inv1 = 1.0f / lacc[2];
    const int row0 = w * 16 + g;

    float* outs = (float*)(smem + OFF_OUT);   // [c][t], stride OSTR
#pragma unroll
    for (int jc = 0; jc < 8; jc++) {
        int c = jc * 8 + tg * 2;
        outs[(c + 0) * OSTR + row0]     = o[jc][0] * inv0;
        outs[(c + 1) * OSTR + row0]     = o[jc][1] * inv0;
        outs[(c + 0) * OSTR + row0 + 8] = o[jc][2] * inv1;
        outs[(c + 1) * OSTR + row0 + 8] = o[jc][3] * inv1;
    }
    __syncthreads();
#pragma unroll
    for (int it = 0; it < 8; it++) {
        int task = tid + it * 256;           // (c, t4): 64 x 32
        int c  = task >> 5;
        int t4 = (task & 31) << 2;
        *(float4*)(outg + (size_t)c * SEQ + t0 + t4) =
            *(const float4*)(outs + c * OSTR + t4);
    }
}

extern "C" void kernel_launch(void* const* d_in, const int* in_sizes, int n_in,
                              void* d_out, int out_size) {
    const float* qkv = (const float*)d_in[0];
    float* out = (float*)d_out;
    cvt_kv<<<4096, 256>>>(qkv);
    cudaFuncSetAttribute(qkv_attn_async,
                         cudaFuncAttributeMaxDynamicSharedMemorySize, SMEM_BYTES);
    dim3 grid(SEQ / 128, 32);
    qkv_attn_async<<<grid, 256, SMEM_BYTES>>>(qkv, out);
}